// round 16
// baseline (speedup 1.0000x reference)
#include <cuda_runtime.h>
#include <cstdint>

// RecurrentDNNC: y_t = relu(M x_t + B y_{t-1} + c); out_t = sigmoid(W2 y_t + b2)
// CHUNK=WARM=16, 4096 one-warp blocks. cp.async fold-in-place: raw x window
// (528 float4) streamed to SMEM, folded float2 overwrites the buffer's lower
// half (hazard-free batching), output staging aliases the dead upper half.
// smem 8.5KB + ~60 regs -> ~26 CTAs/SM (2x R15 occupancy).

#define SEQ     (1 << 21)
#define BLOCK   32
#define CHUNK   16
#define WARM    16                       // == CHUNK: warm window = neighbor strip
#define GRID    (SEQ / (BLOCK * CHUNK))  // 4096 blocks
#define NSTRIP  (BLOCK + 1)              // strips -1..31
#define NELEM   (NSTRIP * CHUNK)         // 528 float4 per block
#define NBATCH  17                       // 17*32 = 544 slots (16 dummy)
#define SMEM_BYTES (NBATCH * BLOCK * 16) // 8704: raw float4 buffer
#define SO_OFF  4352                     // out staging aliases dead upper half

__device__ __forceinline__ float ex2_approx(float x) {
    float r; asm("ex2.approx.f32 %0, %1;" : "=f"(r) : "f"(x)); return r;
}
__device__ __forceinline__ float rcp_approx(float x) {
    float r; asm("rcp.approx.f32 %0, %1;" : "=f"(r) : "f"(x)); return r;
}
__device__ __forceinline__ void cp_async16(uint32_t dst, const void* src) {
    asm volatile("cp.async.cg.shared.global [%0], [%1], 16;" :: "r"(dst), "l"(src));
}
__device__ __forceinline__ void cp_commit() { asm volatile("cp.async.commit_group;"); }
__device__ __forceinline__ void cp_wait0()  { asm volatile("cp.async.wait_group 0;"); }

__global__ void __launch_bounds__(BLOCK, 26)
rdnnc_kernel(const float4* __restrict__ x,
             const float*  __restrict__ W1, const float* __restrict__ b1,
             const float*  __restrict__ Wd, const float* __restrict__ bd,
             const float*  __restrict__ W2, const float* __restrict__ b2,
             float4*       __restrict__ out4)
{
    __shared__ __align__(16) char smem[SMEM_BYTES];
    const float4* raw  = reinterpret_cast<const float4*>(smem);
    float2*       ssf  = reinterpret_cast<float2*>(smem);        // folded, in-place
    const float4* ssf4 = reinterpret_cast<const float4*>(smem);  // pair view
    float4*       so   = reinterpret_cast<float4*>(smem + SO_OFF);
    const uint32_t raw_s = (uint32_t)__cvta_generic_to_shared(smem);

    const int tid       = threadIdx.x;
    const int blockBase = (int)blockIdx.x * (BLOCK * CHUNK) - WARM;  // step of e=0

    // ---- issue ALL x loads first (no registers consumed; stays in flight) ----
    #pragma unroll
    for (int b = 0; b < NBATCH; ++b) {
        const int e = b * BLOCK + tid;               // coalesced per batch
        int g = blockBase + e;
        g = min(max(g, 0), SEQ - 1);                 // dummy/OOB slots: value unused
        cp_async16(raw_s + (uint32_t)(e << 4), x + g);
    }
    cp_commit();

    // ---- fold parameters while loads fly (tiny L1/L2-resident loads) ----
    const float A00 = Wd[0], A01 = Wd[1], B00 = Wd[2], B01 = Wd[3];
    const float A10 = Wd[4], A11 = Wd[5], B10 = Wd[6], B11 = Wd[7];

    const float M00 = A00*W1[0] + A01*W1[4];
    const float M01 = A00*W1[1] + A01*W1[5];
    const float M02 = A00*W1[2] + A01*W1[6];
    const float M03 = A00*W1[3] + A01*W1[7];
    const float M10 = A10*W1[0] + A11*W1[4];
    const float M11 = A10*W1[1] + A11*W1[5];
    const float M12 = A10*W1[2] + A11*W1[6];
    const float M13 = A10*W1[3] + A11*W1[7];

    const float c0 = A00*b1[0] + A01*b1[1] + bd[0];
    const float c1 = A10*b1[0] + A11*b1[1] + bd[1];

    const float L2E = 1.4426950408889634f;
    const float w00 = -L2E*W2[0], w01 = -L2E*W2[1];
    const float w10 = -L2E*W2[2], w11 = -L2E*W2[3];
    const float v0  = -L2E*b2[0], v1  = -L2E*b2[1];

    cp_wait0();
    __syncwarp();                                    // cross-lane visibility

    // ---- fold in place: folded float2 idx = 16s + 2*((j>>1)^(s&7)) + (j&1)
    // (pair-preserving swizzle -> warm/main read LDS.128 conflict-free).
    // Batch k writes bytes [256k,256k+256); batch k'>k reads [512k',..): safe.
    auto fold_store = [&](int e, float4 v) {
        const int s  = e >> 4;
        const int j  = e & 15;
        const int ix = 16*s + 2*(((j >> 1) ^ (s & 7))) + (j & 1);
        const float s0 = fmaf(M00,v.x, fmaf(M01,v.y, fmaf(M02,v.z, fmaf(M03,v.w, c0))));
        const float s1 = fmaf(M10,v.x, fmaf(M11,v.y, fmaf(M12,v.z, fmaf(M13,v.w, c1))));
        ssf[ix] = make_float2(s0, s1);
    };
    {   // batch 0: read-all then write-all (in-place overlap within batch)
        const float4 v = raw[tid];
        __syncwarp();
        fold_store(tid, v);
    }
    #pragma unroll
    for (int b = 1; b < NBATCH; ++b) {
        const int e = b * BLOCK + tid;
        fold_store(e, raw[e]);
    }
    __syncwarp();                                    // folds visible to all lanes

    // ---- recurrence ----
    float y0_ = 0.f, y1_ = 0.f;
    auto step = [&](float sx, float sy) {
        const float n0 = fmaxf(fmaf(B00,y0_, fmaf(B01,y1_, sx)), 0.f);
        const float n1 = fmaxf(fmaf(B10,y0_, fmaf(B11,y1_, sy)), 0.f);
        y0_ = n0; y1_ = n1;
    };

    // warm: strip tid (= previous 16 steps). Block 0 / thread 0: exact y=0 start.
    if ((blockIdx.x | tid) != 0) {
        #pragma unroll
        for (int jp = 0; jp < 8; ++jp) {
            const float4 two = ssf4[8*tid + (jp ^ (tid & 7))];   // steps 2jp,2jp+1
            step(two.x, two.y);
            step(two.z, two.w);
        }
    }

    // main: strip tid+1; head + swizzled staging, then one coalesced drain
    const int sm     = tid + 1;
    const int o4base = (int)blockIdx.x * 256;    // block covers 256 float4 of out

    #pragma unroll
    for (int jp = 0; jp < 8; ++jp) {
        const float4 two = ssf4[8*sm + (jp ^ (sm & 7))];
        step(two.x, two.y);
        const float z0 = fmaf(w00,y0_, fmaf(w01,y1_, v0));
        const float z1 = fmaf(w10,y0_, fmaf(w11,y1_, v1));
        const float r0 = rcp_approx(1.f + ex2_approx(z0));
        const float r1 = rcp_approx(1.f + ex2_approx(z1));

        step(two.z, two.w);
        const float z2 = fmaf(w00,y0_, fmaf(w01,y1_, v0));
        const float z3 = fmaf(w10,y0_, fmaf(w11,y1_, v1));
        const float r2 = rcp_approx(1.f + ex2_approx(z2));
        const float r3 = rcp_approx(1.f + ex2_approx(z3));

        so[tid * 8 + ((tid ^ jp) & 7)] = make_float4(r0, r1, r2, r3);
    }
    __syncwarp();

    #pragma unroll
    for (int l = 0; l < 8; ++l) {                 // drain: 128B contiguous per strip
        const int e = l * BLOCK + tid;
        const int u = e >> 3;                     // strip (8 float4 of out each)
        const int p = e & 7;
        out4[o4base + u * 8 + p] = so[u * 8 + ((u ^ p) & 7)];
    }
}

extern "C" void kernel_launch(void* const* d_in, const int* in_sizes, int n_in,
                              void* d_out, int out_size)
{
    rdnnc_kernel<<<GRID, BLOCK>>>(
        (const float4*)d_in[0],
        (const float*)d_in[1], (const float*)d_in[2],
        (const float*)d_in[3], (const float*)d_in[4],
        (const float*)d_in[5], (const float*)d_in[6],
        (float4*)d_out);
}

// round 17
// speedup vs baseline: 1.0570x; 1.0570x over previous
#include <cuda_runtime.h>
#include <cstdint>

// RecurrentDNNC: y_t = relu(M x_t + B y_{t-1} + c); out_t = sigmoid(W2 y_t + b2)
// CHUNK=WARM=16, 4096 one-warp blocks. x window loaded with ONE cp.async.bulk
// (TMA DMA path — bypasses per-SM LDG miss-tracking cap) into SMEM, folded
// in place, then warm (strip tid) + main (strip tid+1) recurrence.

#define SEQ     (1 << 21)
#define BLOCK   32
#define CHUNK   16
#define WARM    16                        // == CHUNK: warm window = neighbor strip
#define GRID    (SEQ / (BLOCK * CHUNK))   // 4096 blocks
#define NSTRIP  (BLOCK + 1)               // strips -1..31
#define NELEM   (NSTRIP * CHUNK)          // 528 float4 per block
#define RAW_BYTES (NELEM * 16)            // 8448
#define SO_OFF  4352                      // out staging aliases dead upper half
#define MBAR_OFF RAW_BYTES                // mbarrier after raw buffer
#define SMEM_BYTES (RAW_BYTES + 16)

__device__ __forceinline__ float ex2_approx(float x) {
    float r; asm("ex2.approx.f32 %0, %1;" : "=f"(r) : "f"(x)); return r;
}
__device__ __forceinline__ float rcp_approx(float x) {
    float r; asm("rcp.approx.f32 %0, %1;" : "=f"(r) : "f"(x)); return r;
}

__global__ void __launch_bounds__(BLOCK, 26)
rdnnc_kernel(const float4* __restrict__ x,
             const float*  __restrict__ W1, const float* __restrict__ b1,
             const float*  __restrict__ Wd, const float* __restrict__ bd,
             const float*  __restrict__ W2, const float* __restrict__ b2,
             float4*       __restrict__ out4)
{
    __shared__ __align__(128) char smem[SMEM_BYTES];
    const float4* raw  = reinterpret_cast<const float4*>(smem);
    float2*       ssf  = reinterpret_cast<float2*>(smem);        // folded, in-place
    const float4* ssf4 = reinterpret_cast<const float4*>(smem);  // pair view
    float4*       so   = reinterpret_cast<float4*>(smem + SO_OFF);
    const uint32_t smem_s = (uint32_t)__cvta_generic_to_shared(smem);
    const uint32_t mbar_s = smem_s + MBAR_OFF;

    const int tid       = threadIdx.x;
    const int blockBase = (int)blockIdx.x * (BLOCK * CHUNK) - WARM;  // step of e=0

    // ---- one bulk DMA for the whole x window (block 0: shift 16 elems) ----
    const bool head    = (blockIdx.x == 0);
    const uint32_t dst = smem_s + (head ? 256u : 0u);
    const float4*  src = x + (head ? 0 : blockBase);
    const uint32_t nbytes = head ? (RAW_BYTES - 256u) : RAW_BYTES;

    if (tid == 0) {
        asm volatile("mbarrier.init.shared.b64 [%0], 1;" :: "r"(mbar_s) : "memory");
    }
    __syncwarp();
    if (tid == 0) {
        asm volatile("mbarrier.arrive.expect_tx.shared.b64 _, [%0], %1;"
                     :: "r"(mbar_s), "r"(nbytes) : "memory");
        asm volatile("cp.async.bulk.shared::cta.global.mbarrier::complete_tx::bytes "
                     "[%0], [%1], %2, [%3];"
                     :: "r"(dst), "l"(src), "r"(nbytes), "r"(mbar_s) : "memory");
    }

    // ---- fold parameters while the DMA flies (tiny L1/L2-resident loads) ----
    const float A00 = Wd[0], A01 = Wd[1], B00 = Wd[2], B01 = Wd[3];
    const float A10 = Wd[4], A11 = Wd[5], B10 = Wd[6], B11 = Wd[7];

    const float M00 = A00*W1[0] + A01*W1[4];
    const float M01 = A00*W1[1] + A01*W1[5];
    const float M02 = A00*W1[2] + A01*W1[6];
    const float M03 = A00*W1[3] + A01*W1[7];
    const float M10 = A10*W1[0] + A11*W1[4];
    const float M11 = A10*W1[1] + A11*W1[5];
    const float M12 = A10*W1[2] + A11*W1[6];
    const float M13 = A10*W1[3] + A11*W1[7];

    const float c0 = A00*b1[0] + A01*b1[1] + bd[0];
    const float c1 = A10*b1[0] + A11*b1[1] + bd[1];

    const float L2E = 1.4426950408889634f;
    const float w00 = -L2E*W2[0], w01 = -L2E*W2[1];
    const float w10 = -L2E*W2[2], w11 = -L2E*W2[3];
    const float v0  = -L2E*b2[0], v1  = -L2E*b2[1];

    // ---- wait for the DMA (acquire) ----
    {
        uint32_t done;
        do {
            asm volatile(
                "{\n\t.reg .pred p;\n\t"
                "mbarrier.try_wait.parity.acquire.cta.shared::cta.b64 p, [%1], 0, 0x989680;\n\t"
                "selp.b32 %0, 1, 0, p;\n\t}"
                : "=r"(done) : "r"(mbar_s) : "memory");
        } while (!done);
    }
    __syncwarp();

    // ---- fold in place: folded float2 idx = 16s + 2*((j>>1)^(s&7)) + (j&1)
    // (pair-preserving swizzle -> warm/main read LDS.128 conflict-free).
    // Batch k writes bytes [256k,256k+256); batch k'>k reads [512k',..): safe.
    auto fold_store = [&](int e, float4 v) {
        const int s  = e >> 4;
        const int j  = e & 15;
        const int ix = 16*s + 2*(((j >> 1) ^ (s & 7))) + (j & 1);
        const float s0 = fmaf(M00,v.x, fmaf(M01,v.y, fmaf(M02,v.z, fmaf(M03,v.w, c0))));
        const float s1 = fmaf(M10,v.x, fmaf(M11,v.y, fmaf(M12,v.z, fmaf(M13,v.w, c1))));
        ssf[ix] = make_float2(s0, s1);
    };
    {   // batch 0: read-all then write-all (in-place overlap within batch)
        const float4 v = raw[tid];
        __syncwarp();
        fold_store(tid, v);
    }
    #pragma unroll
    for (int b = 1; b < 17; ++b) {
        const int e = b * BLOCK + tid;
        if (e < NELEM) fold_store(e, raw[e]);
    }
    __syncwarp();                                    // folds visible to all lanes

    // ---- recurrence ----
    float y0_ = 0.f, y1_ = 0.f;
    auto step = [&](float sx, float sy) {
        const float n0 = fmaxf(fmaf(B00,y0_, fmaf(B01,y1_, sx)), 0.f);
        const float n1 = fmaxf(fmaf(B10,y0_, fmaf(B11,y1_, sy)), 0.f);
        y0_ = n0; y1_ = n1;
    };

    // warm: strip tid (= previous 16 steps). Block 0 / thread 0: exact y=0 start.
    if ((blockIdx.x | tid) != 0) {
        #pragma unroll
        for (int jp = 0; jp < 8; ++jp) {
            const float4 two = ssf4[8*tid + (jp ^ (tid & 7))];   // steps 2jp,2jp+1
            step(two.x, two.y);
            step(two.z, two.w);
        }
    }

    // main: strip tid+1; head + swizzled staging, then one coalesced drain
    const int sm     = tid + 1;
    const int o4base = (int)blockIdx.x * 256;    // block covers 256 float4 of out

    #pragma unroll
    for (int jp = 0; jp < 8; ++jp) {
        const float4 two = ssf4[8*sm + (jp ^ (sm & 7))];
        step(two.x, two.y);
        const float z0 = fmaf(w00,y0_, fmaf(w01,y1_, v0));
        const float z1 = fmaf(w10,y0_, fmaf(w11,y1_, v1));
        const float r0 = rcp_approx(1.f + ex2_approx(z0));
        const float r1 = rcp_approx(1.f + ex2_approx(z1));

        step(two.z, two.w);
        const float z2 = fmaf(w00,y0_, fmaf(w01,y1_, v0));
        const float z3 = fmaf(w10,y0_, fmaf(w11,y1_, v1));
        const float r2 = rcp_approx(1.f + ex2_approx(z2));
        const float r3 = rcp_approx(1.f + ex2_approx(z3));

        so[tid * 8 + ((tid ^ jp) & 7)] = make_float4(r0, r1, r2, r3);
    }
    __syncwarp();

    #pragma unroll
    for (int l = 0; l < 8; ++l) {                 // drain: 128B contiguous per strip
        const int e = l * BLOCK + tid;
        const int u = e >> 3;                     // strip (8 float4 of out each)
        const int p = e & 7;
        out4[o4base + u * 8 + p] = so[u * 8 + ((u ^ p) & 7)];
    }
}

extern "C" void kernel_launch(void* const* d_in, const int* in_sizes, int n_in,
                              void* d_out, int out_size)
{
    rdnnc_kernel<<<GRID, BLOCK>>>(
        (const float4*)d_in[0],
        (const float*)d_in[1], (const float*)d_in[2],
        (const float*)d_in[3], (const float*)d_in[4],
        (const float*)d_in[5], (const float*)d_in[6],
        (float4*)d_out);
}